// round 15
// baseline (speedup 1.0000x reference)
#include <cuda_runtime.h>
#include <cstdint>
#include <cstddef>

// out[t, e] = cos(t) * rowsum(W[e,:]) + b[e]
// T = 65536, E = 1024. Pure store-bound: 256 MB fp32 output. x never read.
//
// R14 -> R15: more write bytes in flight per SM. R14 (2 blocks/SM, NBUF=3)
// allows 2x2x32KB = 128KB outstanding per SM and sits at DRAM=64% with
// nothing else saturated -> store MLP is the binder. Switch to ONE block
// per SM (grid 148) with 224KB smem: NBUF=7 ring of 32KB tiles,
// wait_group.read 6 -> up to 6 outstanding bulk stores (192KB) per SM.
// Dynamic tile scheduling + prefetched tile index retained (R14's win).

#define EDIM        1024
#define THREADS     256
#define TROWS       8                          // t-rows per tile
#define TILE_FLOATS (TROWS * EDIM)             // 8192 floats
#define TILE_BYTES  (TILE_FLOATS * 4)          // 32 KB
#define NBUF        7                          // 7 * 32KB = 224KB smem
#define GRID        148                        // 1 block/SM

__device__ unsigned int g_tile_ctr;

__global__ void pe_reset_kernel() { g_tile_ctr = 0; }

__device__ __forceinline__ uint32_t smem_u32(const void* p) {
    uint32_t a;
    asm("{ .reg .u64 t; cvta.to.shared.u64 t, %1; cvt.u32.u64 %0, t; }"
        : "=r"(a) : "l"(p));
    return a;
}

extern __shared__ float sbuf[];                // NBUF * TILE_FLOATS = 224 KB

__global__ __launch_bounds__(THREADS)
void pe_tma_kernel(const float* __restrict__ W,   // [E, 8]
                   const float* __restrict__ b,   // [E]
                   float* __restrict__ out,       // [T, E]
                   int T)
{
    const int i = threadIdx.x;                 // 0..255 -> e block [4i, 4i+4)

    // --- per-thread constants: a_k = sum_q W[4i+k, q] (registers) ---
    const float4* W4 = reinterpret_cast<const float4*>(W) + (size_t)i * 8;
    float a0, a1, a2, a3;
    {
        float4 w0 = W4[0], w1 = W4[1];
        float4 w2 = W4[2], w3 = W4[3];
        float4 w4 = W4[4], w5 = W4[5];
        float4 w6 = W4[6], w7 = W4[7];
        a0 = (w0.x + w0.y) + (w0.z + w0.w) + (w1.x + w1.y) + (w1.z + w1.w);
        a1 = (w2.x + w2.y) + (w2.z + w2.w) + (w3.x + w3.y) + (w3.z + w3.w);
        a2 = (w4.x + w4.y) + (w4.z + w4.w) + (w5.x + w5.y) + (w5.z + w5.w);
        a3 = (w6.x + w6.y) + (w6.z + w6.w) + (w7.x + w7.y) + (w7.z + w7.w);
    }
    const float4 bb = reinterpret_cast<const float4*>(b)[i];

    __shared__ float cost[TROWS];
    __shared__ int   tslot[2];                 // double-buffered next-tile idx

    const int ntiles = T / TROWS;              // 8192

    // Prologue: fetch first tile.
    if (i == 0)
        tslot[0] = (int)atomicAdd(&g_tile_ctr, 1u);
    __syncthreads();

    int iter = 0;
    for (;; ++iter) {
        const int tile = tslot[iter & 1];
        if (tile >= ntiles) break;

        float4* buf4 =
            reinterpret_cast<float4*>(sbuf + (iter % NBUF) * TILE_FLOATS);
        const int t0 = tile * TROWS;

        if (i == 0) {
            // Prefetch next tile index (hidden behind this tile's work).
            tslot[(iter + 1) & 1] = (int)atomicAdd(&g_tile_ctr, 1u);
            // Buffer reuse: allow NBUF-1 = 6 newer bulk-store groups pending.
            if (iter >= NBUF)
                asm volatile("cp.async.bulk.wait_group.read 6;" ::: "memory");
        }
        if (i < TROWS)
            cost[i] = cosf((float)(t0 + i));
        __syncthreads();                       // wait + cost + tslot ordered

        #pragma unroll
        for (int r = 0; r < TROWS; ++r) {
            const float c = cost[r];
            float4 v;
            v.x = fmaf(c, a0, bb.x);
            v.y = fmaf(c, a1, bb.y);
            v.z = fmaf(c, a2, bb.z);
            v.w = fmaf(c, a3, bb.w);
            buf4[r * (EDIM / 4) + i] = v;      // STS.128, conflict-free
        }

        asm volatile("fence.proxy.async.shared::cta;" ::: "memory");
        __syncthreads();                       // all STS + fence before commit

        if (i == 0) {
            const uint32_t s = smem_u32(buf4);
            float* g = out + (size_t)t0 * EDIM;
            asm volatile(
                "cp.async.bulk.global.shared::cta.bulk_group [%0], [%1], %2;"
                :: "l"(g), "r"(s), "n"(TILE_BYTES) : "memory");
            asm volatile("cp.async.bulk.commit_group;" ::: "memory");
        }
    }

    // Drain all outstanding bulk stores before exit.
    if (i == 0)
        asm volatile("cp.async.bulk.wait_group 0;" ::: "memory");
}

extern "C" void kernel_launch(void* const* d_in, const int* in_sizes, int n_in,
                              void* d_out, int out_size)
{
    // Identify W (E*8 elems) and b (E elems) by size; x is unused.
    const float* W = nullptr;
    const float* b = nullptr;
    for (int k = 0; k < n_in; ++k) {
        if (in_sizes[k] == EDIM * 8)      W = (const float*)d_in[k];
        else if (in_sizes[k] == EDIM)     b = (const float*)d_in[k];
    }
    if (!W && n_in >= 2) W = (const float*)d_in[1];
    if (!b && n_in >= 3) b = (const float*)d_in[2];

    const int T = out_size / EDIM;             // 65536

    static bool attr_set = false;
    if (!attr_set) {
        cudaFuncSetAttribute(pe_tma_kernel,
                             cudaFuncAttributeMaxDynamicSharedMemorySize,
                             NBUF * TILE_BYTES);
        attr_set = true;
    }

    pe_reset_kernel<<<1, 1>>>();
    pe_tma_kernel<<<GRID, THREADS, NBUF * TILE_BYTES>>>(W, b, (float*)d_out, T);
}

// round 16
// speedup vs baseline: 1.1798x; 1.1798x over previous
#include <cuda_runtime.h>
#include <cstdint>
#include <cstddef>

// out[t, e] = cos(t) * rowsum(W[e,:]) + b[e]
// T = 65536, E = 1024. Pure store-bound: 256 MB fp32 output. x never read.
//
// R15 -> R16: warp-autonomous pipelines. R15 proved the binder is block-wide
// barrier serialization (1 block/SM collapsed to 50% DRAM). So eliminate
// block sync entirely: each warp is an independent producer with its own
// 3-deep 4KB ring, its own bulk-store group, and its own sharded atomic
// work counter (8 counters, 256B apart). Work unit = one t-row (4KB,
// gmem-contiguous). Per-e constants live in shared LUTs (built once) so
// registers stay low. Zero BAR.SYNC in the hot loop; 16 decoupled
// pipelines/SM hide each other's latency.

#define EDIM        1024
#define THREADS     256                        // 8 warps/block
#define NWARP       8
#define ROW_FLOATS  EDIM                       // one t-row = 4 KB
#define NBUF        3                          // ring: 3 x 4KB per warp
#define GRID        296                        // 2 blocks/SM * 148 SMs
#define NSTRIPE     8192                       // rows per warp-slot stripe (65536/8)

__device__ unsigned int g_ctr[NWARP * 64];     // 256B stride between counters

__global__ void pe_reset_kernel() {
    if (threadIdx.x < NWARP) g_ctr[threadIdx.x * 64] = 0u;
}

__device__ __forceinline__ uint32_t smem_u32(const void* p) {
    uint32_t a;
    asm("{ .reg .u64 t; cvta.to.shared.u64 t, %1; cvt.u32.u64 %0, t; }"
        : "=r"(a) : "l"(p));
    return a;
}

extern __shared__ float sbuf[];                // NWARP * NBUF * 1024 floats = 96 KB

__global__ __launch_bounds__(THREADS)
void pe_tma_kernel(const float* __restrict__ W,   // [E, 8]
                   const float* __restrict__ b,   // [E]
                   float* __restrict__ out,       // [T, E]
                   int T)
{
    const int i    = threadIdx.x;
    const int w    = i >> 5;                   // warp 0..7
    const int lane = i & 31;

    // --- shared LUTs: Asum4[g] = rowsums of W rows 4g..4g+3, Bb4[g] = b ---
    __shared__ float4 Ash[EDIM / 4];           // 4 KB
    __shared__ float4 Bsh[EDIM / 4];           // 4 KB
    {
        const float4* W4 = reinterpret_cast<const float4*>(W) + (size_t)i * 8;
        float4 w0 = W4[0], w1 = W4[1];
        float4 w2 = W4[2], w3 = W4[3];
        float4 w4 = W4[4], w5 = W4[5];
        float4 w6 = W4[6], w7 = W4[7];
        float4 a;
        a.x = (w0.x + w0.y) + (w0.z + w0.w) + (w1.x + w1.y) + (w1.z + w1.w);
        a.y = (w2.x + w2.y) + (w2.z + w2.w) + (w3.x + w3.y) + (w3.z + w3.w);
        a.z = (w4.x + w4.y) + (w4.z + w4.w) + (w5.x + w5.y) + (w5.z + w5.w);
        a.w = (w6.x + w6.y) + (w6.z + w6.w) + (w7.x + w7.y) + (w7.z + w7.w);
        Ash[i] = a;
        Bsh[i] = reinterpret_cast<const float4*>(b)[i];
    }
    __syncthreads();                           // the ONLY block barrier

    // Per-warp ring buffer base (3 x 1024 floats).
    float4* ring = reinterpret_cast<float4*>(sbuf + w * (NBUF * ROW_FLOATS));
    unsigned int* ctr = &g_ctr[w * 64];

    // Prologue: lane 0 fetches first work unit for this warp's stripe.
    int u_reg = 0;
    if (lane == 0) u_reg = (int)atomicAdd(ctr, 1u);

    int iter = 0;
    for (;; ++iter) {
        const int u = __shfl_sync(0xffffffffu, u_reg, 0);
        if (u >= NSTRIPE) break;
        const int t = u * NWARP + w;           // this warp's row

        // Prefetch next unit (latency hidden behind this row's work).
        if (lane == 0) {
            u_reg = (int)atomicAdd(ctr, 1u);
            // Reuse slot (iter-NBUF): allow NBUF-1 = 2 newer groups pending.
            if (iter >= NBUF)
                asm volatile("cp.async.bulk.wait_group.read 2;" ::: "memory");
        }
        __syncwarp();                          // lanes wait for lane0's wait

        float4* buf = ring + (iter % NBUF) * (ROW_FLOATS / 4);
        const float c = cosf((float)t);        // all lanes, same value

        #pragma unroll
        for (int k = 0; k < 8; ++k) {
            const int g = lane + 32 * k;       // e-group 0..255
            const float4 a  = Ash[g];
            const float4 bb = Bsh[g];
            float4 v;
            v.x = fmaf(c, a.x, bb.x);
            v.y = fmaf(c, a.y, bb.y);
            v.z = fmaf(c, a.z, bb.z);
            v.w = fmaf(c, a.w, bb.w);
            buf[g] = v;                        // STS.128, conflict-free
        }
        __syncwarp();                          // all lanes' STS done

        if (lane == 0) {
            asm volatile("fence.proxy.async.shared::cta;" ::: "memory");
            const uint32_t s = smem_u32(buf);
            float* g = out + (size_t)t * EDIM;
            asm volatile(
                "cp.async.bulk.global.shared::cta.bulk_group [%0], [%1], %2;"
                :: "l"(g), "r"(s), "n"(ROW_FLOATS * 4) : "memory");
            asm volatile("cp.async.bulk.commit_group;" ::: "memory");
        }
    }

    // Drain this warp's outstanding bulk stores.
    if (lane == 0)
        asm volatile("cp.async.bulk.wait_group 0;" ::: "memory");
}

extern "C" void kernel_launch(void* const* d_in, const int* in_sizes, int n_in,
                              void* d_out, int out_size)
{
    // Identify W (E*8 elems) and b (E elems) by size; x is unused.
    const float* W = nullptr;
    const float* b = nullptr;
    for (int k = 0; k < n_in; ++k) {
        if (in_sizes[k] == EDIM * 8)      W = (const float*)d_in[k];
        else if (in_sizes[k] == EDIM)     b = (const float*)d_in[k];
    }
    if (!W && n_in >= 2) W = (const float*)d_in[1];
    if (!b && n_in >= 3) b = (const float*)d_in[2];

    const int T = out_size / EDIM;             // 65536

    static bool attr_set = false;
    if (!attr_set) {
        cudaFuncSetAttribute(pe_tma_kernel,
                             cudaFuncAttributeMaxDynamicSharedMemorySize,
                             NWARP * NBUF * ROW_FLOATS * 4);   // 96 KB
        attr_set = true;
    }

    pe_reset_kernel<<<1, 32>>>();
    pe_tma_kernel<<<GRID, THREADS, NWARP * NBUF * ROW_FLOATS * 4>>>(
        W, b, (float*)d_out, T);
}

// round 17
// speedup vs baseline: 1.1823x; 1.0021x over previous
#include <cuda_runtime.h>
#include <cstdint>
#include <cstddef>

// out[t, e] = cos(t) * rowsum(W[e,:]) + b[e]
// T = 65536, E = 1024. Pure store-bound: 256 MB fp32 output. x never read.
//
// R16 -> R17: same warp-autonomous architecture (R16's win over block-wide
// barriers), but halve the per-byte loop overhead: work unit 4KB -> 8KB
// (2 rows), 4 warp-pipelines per 128-thread block, 2 blocks/SM -> 8
// independent pipelines/SM, each with a 3-deep 8KB ring (2 pending stores).
// Per-SM pending bytes unchanged (128KB); atomics/fences/commits per byte
// halved; 8KB bulk stores are friendlier to L2/DRAM than 4KB.

#define EDIM        1024
#define THREADS     128                        // 4 warps/block
#define NWARP       4
#define UNIT_ROWS   2
#define UNIT_FLOATS (UNIT_ROWS * EDIM)         // 2048 floats = 8 KB
#define NBUF        3                          // ring: 3 x 8KB per warp
#define GRID        296                        // 2 blocks/SM * 148 SMs
#define NUNITS      (65536 / UNIT_ROWS)        // 32768 row-pairs
#define NSTRIPE     (NUNITS / NWARP)           // 8192 units per warp slot

__device__ unsigned int g_ctr[NWARP * 64];     // 256B stride between counters

__global__ void pe_reset_kernel() {
    if (threadIdx.x < NWARP) g_ctr[threadIdx.x * 64] = 0u;
}

__device__ __forceinline__ uint32_t smem_u32(const void* p) {
    uint32_t a;
    asm("{ .reg .u64 t; cvta.to.shared.u64 t, %1; cvt.u32.u64 %0, t; }"
        : "=r"(a) : "l"(p));
    return a;
}

extern __shared__ float sbuf[];                // NWARP * NBUF * 2048 floats = 96 KB

__global__ __launch_bounds__(THREADS)
void pe_tma_kernel(const float* __restrict__ W,   // [E, 8]
                   const float* __restrict__ b,   // [E]
                   float* __restrict__ out,       // [T, E]
                   int T)
{
    const int i    = threadIdx.x;
    const int w    = i >> 5;                   // warp 0..3
    const int lane = i & 31;

    // --- shared LUTs: Ash[g] = rowsums of W rows 4g..4g+3, Bsh[g] = b ---
    __shared__ float4 Ash[EDIM / 4];           // 4 KB
    __shared__ float4 Bsh[EDIM / 4];           // 4 KB
    #pragma unroll
    for (int rep = 0; rep < 2; ++rep) {
        const int g = i + rep * THREADS;       // 0..255
        const float4* W4 = reinterpret_cast<const float4*>(W) + (size_t)g * 8;
        float4 w0 = W4[0], w1 = W4[1];
        float4 w2 = W4[2], w3 = W4[3];
        float4 w4 = W4[4], w5 = W4[5];
        float4 w6 = W4[6], w7 = W4[7];
        float4 a;
        a.x = (w0.x + w0.y) + (w0.z + w0.w) + (w1.x + w1.y) + (w1.z + w1.w);
        a.y = (w2.x + w2.y) + (w2.z + w2.w) + (w3.x + w3.y) + (w3.z + w3.w);
        a.z = (w4.x + w4.y) + (w4.z + w4.w) + (w5.x + w5.y) + (w5.z + w5.w);
        a.w = (w6.x + w6.y) + (w6.z + w6.w) + (w7.x + w7.y) + (w7.z + w7.w);
        Ash[g] = a;
        Bsh[g] = reinterpret_cast<const float4*>(b)[g];
    }
    __syncthreads();                           // the ONLY block barrier

    // Per-warp ring buffer base (3 x 2048 floats).
    float4* ring = reinterpret_cast<float4*>(sbuf + w * (NBUF * UNIT_FLOATS));
    unsigned int* ctr = &g_ctr[w * 64];

    // Prologue: lane 0 fetches first work unit for this warp's stripe.
    int u_reg = 0;
    if (lane == 0) u_reg = (int)atomicAdd(ctr, 1u);

    int iter = 0;
    for (;; ++iter) {
        const int u = __shfl_sync(0xffffffffu, u_reg, 0);
        if (u >= NSTRIPE) break;
        const int t0 = (u * NWARP + w) * UNIT_ROWS;   // first row of the pair

        // Prefetch next unit; free the ring slot being reused.
        if (lane == 0) {
            u_reg = (int)atomicAdd(ctr, 1u);
            if (iter >= NBUF)
                asm volatile("cp.async.bulk.wait_group.read 2;" ::: "memory");
        }
        __syncwarp();                          // lanes wait for lane0's wait

        float4* buf = ring + (iter % NBUF) * (UNIT_FLOATS / 4);
        const float c0 = cosf((float)t0);
        const float c1 = cosf((float)(t0 + 1));

        #pragma unroll
        for (int k = 0; k < 8; ++k) {
            const int g = lane + 32 * k;       // e-group 0..255
            const float4 a  = Ash[g];
            const float4 bb = Bsh[g];
            float4 v0, v1;
            v0.x = fmaf(c0, a.x, bb.x);  v1.x = fmaf(c1, a.x, bb.x);
            v0.y = fmaf(c0, a.y, bb.y);  v1.y = fmaf(c1, a.y, bb.y);
            v0.z = fmaf(c0, a.z, bb.z);  v1.z = fmaf(c1, a.z, bb.z);
            v0.w = fmaf(c0, a.w, bb.w);  v1.w = fmaf(c1, a.w, bb.w);
            buf[g]       = v0;                 // row t0
            buf[256 + g] = v1;                 // row t0+1
        }
        __syncwarp();                          // all lanes' STS done

        if (lane == 0) {
            asm volatile("fence.proxy.async.shared::cta;" ::: "memory");
            const uint32_t s = smem_u32(buf);
            float* g = out + (size_t)t0 * EDIM;
            asm volatile(
                "cp.async.bulk.global.shared::cta.bulk_group [%0], [%1], %2;"
                :: "l"(g), "r"(s), "n"(UNIT_FLOATS * 4) : "memory");
            asm volatile("cp.async.bulk.commit_group;" ::: "memory");
        }
    }

    // Drain this warp's outstanding bulk stores.
    if (lane == 0)
        asm volatile("cp.async.bulk.wait_group 0;" ::: "memory");
}

extern "C" void kernel_launch(void* const* d_in, const int* in_sizes, int n_in,
                              void* d_out, int out_size)
{
    // Identify W (E*8 elems) and b (E elems) by size; x is unused.
    const float* W = nullptr;
    const float* b = nullptr;
    for (int k = 0; k < n_in; ++k) {
        if (in_sizes[k] == EDIM * 8)      W = (const float*)d_in[k];
        else if (in_sizes[k] == EDIM)     b = (const float*)d_in[k];
    }
    if (!W && n_in >= 2) W = (const float*)d_in[1];
    if (!b && n_in >= 3) b = (const float*)d_in[2];

    const int T = out_size / EDIM;             // 65536

    static bool attr_set = false;
    if (!attr_set) {
        cudaFuncSetAttribute(pe_tma_kernel,
                             cudaFuncAttributeMaxDynamicSharedMemorySize,
                             NWARP * NBUF * UNIT_FLOATS * 4);   // 96 KB
        attr_set = true;
    }

    pe_reset_kernel<<<1, 32>>>();
    pe_tma_kernel<<<GRID, THREADS, NWARP * NBUF * UNIT_FLOATS * 4>>>(
        W, b, (float*)d_out, T);
}